// round 5
// baseline (speedup 1.0000x reference)
#include <cuda_runtime.h>
#include <math_constants.h>

// kNN graph, PyG knn_graph(loop=False): B=16 graphs x n=4096 pts, D=3, k=16.
// Output (float32 flat): [nbr_global | centers | topk_d2], each total_n*K,
// ordering (b*n+i)*K + m (matches reference reshape(-1)).

#define K        16
#define KP1      17            // keep k+1; self entry removed at output
#define NPER     4096
#define TPB      256
#define CPG      (NPER / TPB)  // 16 CTAs per graph
#define PB       16            // pending u64 slots per thread
#define FLUSH_AT 9             // flush when cnt >= 9 (room for 8 more pushes)
#define SLOT_B   (TPB * 8u)    // byte stride between a thread's slots

#define FMA_F32X2(out, a, b, c) \
    asm("fma.rn.f32x2 %0, %1, %2, %3;" : "=l"(out) : "l"(a), "l"(b), "l"(c))
#define MUL_F32X2_(out, a, b) \
    asm("mul.rn.f32x2 %0, %1, %2;" : "=l"(out) : "l"(a), "l"(b))
#define ADD_F32X2_(out, a, b) \
    asm("add.rn.f32x2 %0, %1, %2;" : "=l"(out) : "l"(a), "l"(b))
#define PACK2(out, lo, hi) \
    asm("mov.b64 %0, {%1, %2};" : "=l"(out) : "r"(lo), "r"(hi))
#define UNPACK2(lo, hi, in) \
    asm("mov.b64 {%0, %1}, %2;" : "=r"(lo), "=r"(hi) : "l"(in))

// Branchless predicated push: store packed (dist,idx) iff flag != 0.
// Address comes from a prefix-sum offset (no serial predicated updates).
#define PUSHP(dv, jv, bv, ov)                                                 \
    do {                                                                      \
        unsigned long long kk_;                                               \
        asm("mov.b64 %0, {%1, %2};"                                           \
            : "=l"(kk_) : "r"((unsigned)(jv)), "r"(__float_as_uint(dv)));     \
        const unsigned ad_ = pbase + (unsigned)(ov) * SLOT_B;                 \
        asm volatile(                                                         \
            "{\n\t.reg .pred p;\n\t"                                          \
            "setp.ne.u32 p, %2, 0;\n\t"                                       \
            "@p st.shared.b64 [%0], %1;\n\t}"                                 \
            :: "r"(ad_), "l"(kk_), "r"(bv) : "memory");                       \
    } while (0)

__global__ __launch_bounds__(TPB, 2)
void knn_topk_kernel(const float* __restrict__ pos,
                     float* __restrict__ out,
                     int total_n)
{
    extern __shared__ float smem[];
    float* sx = smem;
    float* sy = smem +     NPER;
    float* sz = smem + 2 * NPER;
    float* ss = smem + 3 * NPER;
    unsigned long long* pend =
        (unsigned long long*)(smem + 4 * NPER);   // [PB][TPB] pending keys

    const int graph = blockIdx.x / CPG;
    const int base  = graph * NPER;
    const float* gp = pos + (size_t)base * 3;

    // Stage graph points (SoA) + squared norms into SMEM.
    for (int p = threadIdx.x; p < NPER; p += TPB) {
        float x = gp[3 * p + 0];
        float y = gp[3 * p + 1];
        float z = gp[3 * p + 2];
        sx[p] = x; sy[p] = y; sz[p] = z;
        ss[p] = fmaf(z, z, fmaf(y, y, x * x));
    }
    __syncthreads();

    const int   tid = threadIdx.x;
    const int   q   = (blockIdx.x % CPG) * TPB + tid;
    const float qx = sx[q], qy = sy[q], qz = sz[q], qs = ss[q];

    unsigned long long qx2, qy2, qz2, qs2, m2;
    {
        const unsigned xb = __float_as_uint(qx), yb = __float_as_uint(qy);
        const unsigned zb = __float_as_uint(qz), sb = __float_as_uint(qs);
        const unsigned nb = __float_as_uint(-2.0f);
        PACK2(qx2, xb, xb); PACK2(qy2, yb, yb); PACK2(qz2, zb, zb);
        PACK2(qs2, sb, sb); PACK2(m2, nb, nb);
    }

    // Sorted K+1 list (ascending float distance; FIFO insert order => ties
    // keep the earlier/lower index, matching jax.lax.top_k). Self (d~0) is
    // kept in the list and removed at output.
    float bd[KP1];
    int   bi[KP1];
#pragma unroll
    for (int m = 0; m < KP1; ++m) { bd[m] = CUDART_INF_F; bi[m] = -1; }
    float worst = CUDART_INF_F;

    int cnt = 0;
    const unsigned pbase = (unsigned)__cvta_generic_to_shared(pend + tid);

#pragma unroll 2
    for (int j0 = 0; j0 < NPER; j0 += 8) {
        const ulonglong2 Xa = *reinterpret_cast<const ulonglong2*>(sx + j0);
        const ulonglong2 Ya = *reinterpret_cast<const ulonglong2*>(sy + j0);
        const ulonglong2 Za = *reinterpret_cast<const ulonglong2*>(sz + j0);
        const ulonglong2 Sa = *reinterpret_cast<const ulonglong2*>(ss + j0);
        const ulonglong2 Xb = *reinterpret_cast<const ulonglong2*>(sx + j0 + 4);
        const ulonglong2 Yb = *reinterpret_cast<const ulonglong2*>(sy + j0 + 4);
        const ulonglong2 Zb = *reinterpret_cast<const ulonglong2*>(sz + j0 + 4);
        const ulonglong2 Sb = *reinterpret_cast<const ulonglong2*>(ss + j0 + 4);

        // d = (qs + s) - 2*dot; f32x2 = two independent fp32 FMAs with the
        // exact op order/rounding of the scalar reference formula.
        unsigned long long dt, tt, dp0, dp1, dp2, dp3;
        MUL_F32X2_(dt, qx2, Xa.x); FMA_F32X2(dt, qy2, Ya.x, dt); FMA_F32X2(dt, qz2, Za.x, dt);
        ADD_F32X2_(tt, Sa.x, qs2); FMA_F32X2(dp0, m2, dt, tt);
        MUL_F32X2_(dt, qx2, Xa.y); FMA_F32X2(dt, qy2, Ya.y, dt); FMA_F32X2(dt, qz2, Za.y, dt);
        ADD_F32X2_(tt, Sa.y, qs2); FMA_F32X2(dp1, m2, dt, tt);
        MUL_F32X2_(dt, qx2, Xb.x); FMA_F32X2(dt, qy2, Yb.x, dt); FMA_F32X2(dt, qz2, Zb.x, dt);
        ADD_F32X2_(tt, Sb.x, qs2); FMA_F32X2(dp2, m2, dt, tt);
        MUL_F32X2_(dt, qx2, Xb.y); FMA_F32X2(dt, qy2, Yb.y, dt); FMA_F32X2(dt, qz2, Zb.y, dt);
        ADD_F32X2_(tt, Sb.y, qs2); FMA_F32X2(dp3, m2, dt, tt);

        unsigned u0, u1, u2, u3, u4, u5, u6, u7;
        UNPACK2(u0, u1, dp0); UNPACK2(u2, u3, dp1);
        UNPACK2(u4, u5, dp2); UNPACK2(u6, u7, dp3);
        const float d0 = __uint_as_float(u0), d1 = __uint_as_float(u1);
        const float d2 = __uint_as_float(u2), d3 = __uint_as_float(u3);
        const float d4 = __uint_as_float(u4), d5 = __uint_as_float(u5);
        const float d6 = __uint_as_float(u6), d7 = __uint_as_float(u7);

        const float mn = fminf(fminf(fminf(d0, d1), fminf(d2, d3)),
                               fminf(fminf(d4, d5), fminf(d6, d7)));
        if (mn < worst) {   // per-lane skip; body below is branchless
            const unsigned b0 = (d0 < worst) ? 1u : 0u;
            const unsigned b1 = (d1 < worst) ? 1u : 0u;
            const unsigned b2 = (d2 < worst) ? 1u : 0u;
            const unsigned b3 = (d3 < worst) ? 1u : 0u;
            const unsigned b4 = (d4 < worst) ? 1u : 0u;
            const unsigned b5 = (d5 < worst) ? 1u : 0u;
            const unsigned b6 = (d6 < worst) ? 1u : 0u;
            const unsigned b7 = (d7 < worst) ? 1u : 0u;
            const unsigned o0 = (unsigned)cnt;
            const unsigned o1 = o0 + b0;
            const unsigned o2 = o1 + b1;
            const unsigned o3 = o2 + b2;
            const unsigned o4 = o3 + b3;
            const unsigned o5 = o4 + b4;
            const unsigned o6 = o5 + b5;
            const unsigned o7 = o6 + b6;
            PUSHP(d0, j0 + 0, b0, o0);
            PUSHP(d1, j0 + 1, b1, o1);
            PUSHP(d2, j0 + 2, b2, o2);
            PUSHP(d3, j0 + 3, b3, o3);
            PUSHP(d4, j0 + 4, b4, o4);
            PUSHP(d5, j0 + 5, b5, o5);
            PUSHP(d6, j0 + 6, b6, o6);
            PUSHP(d7, j0 + 7, b7, o7);
            cnt = (int)(o7 + b7);
        }

        if (__any_sync(0xFFFFFFFFu, cnt >= FLUSH_AT)) {   // warp-uniform
            const int wmax = __reduce_max_sync(0xFFFFFFFFu, cnt);
            const unsigned long long* myp = pend + tid;
#pragma unroll 1
            for (int p = 0; p < wmax; ++p) {
                const unsigned long long kk = myp[(size_t)p * TPB];
                unsigned lo_, hi_;
                UNPACK2(lo_, hi_, kk);
                float dc = (p < cnt) ? __uint_as_float(hi_) : CUDART_INF_F;
                int   ic = (int)lo_;
                if (__any_sync(0xFFFFFFFFu, dc < worst)) {  // uniform guard
#pragma unroll
                    for (int m = 0; m < KP1; ++m) {
                        const bool  sw = dc < bd[m];  // strict '<': FIFO ties
                        const float fo = sw ? bd[m] : dc;
                        const int   io = sw ? bi[m] : ic;
                        bd[m] = sw ? dc : bd[m];
                        bi[m] = sw ? ic : bi[m];
                        dc = fo; ic = io;
                    }
                    worst = bd[KP1 - 1];
                }
            }
            cnt = 0;
        }
    }

    // Final drain.
    {
        const int wmax = __reduce_max_sync(0xFFFFFFFFu, cnt);
        const unsigned long long* myp = pend + tid;
#pragma unroll 1
        for (int p = 0; p < wmax; ++p) {
            const unsigned long long kk = myp[(size_t)p * TPB];
            unsigned lo_, hi_;
            UNPACK2(lo_, hi_, kk);
            float dc = (p < cnt) ? __uint_as_float(hi_) : CUDART_INF_F;
            int   ic = (int)lo_;
            if (__any_sync(0xFFFFFFFFu, dc < worst)) {
#pragma unroll
                for (int m = 0; m < KP1; ++m) {
                    const bool  sw = dc < bd[m];
                    const float fo = sw ? bd[m] : dc;
                    const int   io = sw ? bi[m] : ic;
                    bd[m] = sw ? dc : bd[m];
                    bi[m] = sw ? ic : bi[m];
                    dc = fo; ic = io;
                }
                worst = bd[KP1 - 1];
            }
        }
    }

    // Emit: drop the single self entry (idx == q), keep first K others.
    const int    gq = base + q;
    const size_t Nk = (size_t)total_n * K;
    int w = 0;
#pragma unroll
    for (int m = 0; m < KP1; ++m) {
        if (bi[m] != q && w < K) {
            const size_t e = (size_t)gq * K + w;
            out[e]          = (float)(bi[m] + base);
            out[Nk + e]     = (float)gq;
            out[2 * Nk + e] = bd[m];
            ++w;
        }
    }
}

extern "C" void kernel_launch(void* const* d_in, const int* in_sizes, int n_in,
                              void* d_out, int out_size)
{
    const float* pos = (const float*)d_in[0];
    const int total_n = in_sizes[0] / 3;
    const int ngraphs = total_n / NPER;

    const int smem_bytes = 4 * NPER * (int)sizeof(float)
                         + PB * TPB * (int)sizeof(unsigned long long); // 96 KB
    cudaFuncSetAttribute(knn_topk_kernel,
                         cudaFuncAttributeMaxDynamicSharedMemorySize, smem_bytes);

    knn_topk_kernel<<<ngraphs * CPG, TPB, smem_bytes>>>(pos, (float*)d_out, total_n);
}

// round 6
// speedup vs baseline: 1.4493x; 1.4493x over previous
#include <cuda_runtime.h>
#include <math_constants.h>

// kNN graph, PyG knn_graph(loop=False): B=16 graphs x n=4096 pts, D=3, k=16.
// Output (float32 flat): [nbr_global | centers | topk_d2], each total_n*K,
// ordering (b*n+i)*K + m (matches reference reshape(-1)).

#define K        16
#define KP1      17            // keep k+1; self entry removed at output
#define NPER     4096
#define TPB      256
#define CPG      (NPER / TPB)  // 16 CTAs per graph
#define PB       12            // pending u64 slots per thread
#define FLUSH_AT 5             // flush when cnt >= 5 (8 pushes/block max -> 12)
#define SLOT_B   (TPB * 8u)    // byte stride between a thread's slots (2048)
#define FLUSH_B  (FLUSH_AT * SLOT_B)

#define FMA_F32X2(out, a, b, c) \
    asm("fma.rn.f32x2 %0, %1, %2, %3;" : "=l"(out) : "l"(a), "l"(b), "l"(c))
#define MUL_F32X2_(out, a, b) \
    asm("mul.rn.f32x2 %0, %1, %2;" : "=l"(out) : "l"(a), "l"(b))
#define ADD_F32X2_(out, a, b) \
    asm("add.rn.f32x2 %0, %1, %2;" : "=l"(out) : "l"(a), "l"(b))
#define PACK2(out, lo, hi) \
    asm("mov.b64 %0, {%1, %2};" : "=l"(out) : "r"(lo), "r"(hi))
#define UNPACK2(lo, hi, in) \
    asm("mov.b64 {%0, %1}, %2;" : "=r"(lo), "=r"(hi) : "l"(in))

// Unconditional branchless push: one setp guards the store AND (via selp)
// produces the byte increment {0, SLOT_B}. No branches, no BSSY/BSYNC,
// no serial predicated address mutation (offset advances with plain adds).
#define PUSHB(dv, jv, offin, offout)                                          \
    do {                                                                      \
        unsigned long long kk_;                                               \
        asm("mov.b64 %0, {%1, %2};"                                           \
            : "=l"(kk_) : "r"((unsigned)(jv)), "r"(__float_as_uint(dv)));     \
        unsigned inc_;                                                        \
        asm volatile(                                                         \
            "{\n\t.reg .pred p;\n\t"                                          \
            "setp.lt.f32 p, %1, %2;\n\t"                                      \
            "selp.u32 %0, %3, 0, p;\n\t"                                      \
            "@p st.shared.b64 [%4], %5;\n\t}"                                 \
            : "=r"(inc_)                                                      \
            : "f"(dv), "f"(worst), "n"(SLOT_B),                               \
              "r"(pbase + (offin)), "l"(kk_)                                  \
            : "memory");                                                      \
        (offout) = (offin) + inc_;                                            \
    } while (0)

__global__ __launch_bounds__(TPB, 2)
void knn_topk_kernel(const float* __restrict__ pos,
                     float* __restrict__ out,
                     int total_n)
{
    extern __shared__ float smem[];
    float* sx = smem;
    float* sy = smem +     NPER;
    float* sz = smem + 2 * NPER;
    float* ss = smem + 3 * NPER;
    unsigned long long* pend =
        (unsigned long long*)(smem + 4 * NPER);   // [PB][TPB] pending keys

    const int graph = blockIdx.x / CPG;
    const int base  = graph * NPER;
    const float* gp = pos + (size_t)base * 3;

    // Stage graph points (SoA) + squared norms. ss uses the SAME op order as
    // the dot chain so the self-distance is exactly +0.
    for (int p = threadIdx.x; p < NPER; p += TPB) {
        float x = gp[3 * p + 0];
        float y = gp[3 * p + 1];
        float z = gp[3 * p + 2];
        sx[p] = x; sy[p] = y; sz[p] = z;
        ss[p] = fmaf(z, z, fmaf(y, y, x * x));
    }
    __syncthreads();

    const int   tid = threadIdx.x;
    const int   q   = (blockIdx.x % CPG) * TPB + tid;
    const float qx = sx[q], qy = sy[q], qz = sz[q], qs = ss[q];

    unsigned long long qx2, qy2, qz2, qs2, m2;
    {
        const unsigned xb = __float_as_uint(qx), yb = __float_as_uint(qy);
        const unsigned zb = __float_as_uint(qz), sb = __float_as_uint(qs);
        const unsigned nb = __float_as_uint(-2.0f);
        PACK2(qx2, xb, xb); PACK2(qy2, yb, yb); PACK2(qz2, zb, zb);
        PACK2(qs2, sb, sb); PACK2(m2, nb, nb);
    }

    // Sorted K+1 list (ascending; FIFO order + strict '<' chain => ties keep
    // the earlier/lower index, matching jax.lax.top_k). Self kept, removed
    // at output.
    float bd[KP1];
    int   bi[KP1];
#pragma unroll
    for (int m = 0; m < KP1; ++m) { bd[m] = CUDART_INF_F; bi[m] = -1; }
    float worst = CUDART_INF_F;

    unsigned offb = 0;   // FIFO fill, in bytes (slot stride SLOT_B)
    const unsigned pbase = (unsigned)__cvta_generic_to_shared(pend + tid);

#pragma unroll 2
    for (int j0 = 0; j0 < NPER; j0 += 8) {
        const ulonglong2 Xa = *reinterpret_cast<const ulonglong2*>(sx + j0);
        const ulonglong2 Ya = *reinterpret_cast<const ulonglong2*>(sy + j0);
        const ulonglong2 Za = *reinterpret_cast<const ulonglong2*>(sz + j0);
        const ulonglong2 Sa = *reinterpret_cast<const ulonglong2*>(ss + j0);
        const ulonglong2 Xb = *reinterpret_cast<const ulonglong2*>(sx + j0 + 4);
        const ulonglong2 Yb = *reinterpret_cast<const ulonglong2*>(sy + j0 + 4);
        const ulonglong2 Zb = *reinterpret_cast<const ulonglong2*>(sz + j0 + 4);
        const ulonglong2 Sb = *reinterpret_cast<const ulonglong2*>(ss + j0 + 4);

        // d = (qs + s) - 2*dot; f32x2 = two independent fp32 FMAs with the
        // exact op order/rounding of the scalar reference formula.
        unsigned long long dt, tt, dp0, dp1, dp2, dp3;
        MUL_F32X2_(dt, qx2, Xa.x); FMA_F32X2(dt, qy2, Ya.x, dt); FMA_F32X2(dt, qz2, Za.x, dt);
        ADD_F32X2_(tt, Sa.x, qs2); FMA_F32X2(dp0, m2, dt, tt);
        MUL_F32X2_(dt, qx2, Xa.y); FMA_F32X2(dt, qy2, Ya.y, dt); FMA_F32X2(dt, qz2, Za.y, dt);
        ADD_F32X2_(tt, Sa.y, qs2); FMA_F32X2(dp1, m2, dt, tt);
        MUL_F32X2_(dt, qx2, Xb.x); FMA_F32X2(dt, qy2, Yb.x, dt); FMA_F32X2(dt, qz2, Zb.x, dt);
        ADD_F32X2_(tt, Sb.x, qs2); FMA_F32X2(dp2, m2, dt, tt);
        MUL_F32X2_(dt, qx2, Xb.y); FMA_F32X2(dt, qy2, Yb.y, dt); FMA_F32X2(dt, qz2, Zb.y, dt);
        ADD_F32X2_(tt, Sb.y, qs2); FMA_F32X2(dp3, m2, dt, tt);

        unsigned u0, u1, u2, u3, u4, u5, u6, u7;
        UNPACK2(u0, u1, dp0); UNPACK2(u2, u3, dp1);
        UNPACK2(u4, u5, dp2); UNPACK2(u6, u7, dp3);
        const float d0 = __uint_as_float(u0), d1 = __uint_as_float(u1);
        const float d2 = __uint_as_float(u2), d3 = __uint_as_float(u3);
        const float d4 = __uint_as_float(u4), d5 = __uint_as_float(u5);
        const float d6 = __uint_as_float(u6), d7 = __uint_as_float(u7);

        // Unconditional branchless pushes (entry filtering is useless at warp
        // granularity: P(any lane has a candidate) ~= 1 for every block).
        unsigned o1, o2, o3, o4, o5, o6, o7, o8;
        PUSHB(d0, j0 + 0, offb, o1);
        PUSHB(d1, j0 + 1, o1,   o2);
        PUSHB(d2, j0 + 2, o2,   o3);
        PUSHB(d3, j0 + 3, o3,   o4);
        PUSHB(d4, j0 + 4, o4,   o5);
        PUSHB(d5, j0 + 5, o5,   o6);
        PUSHB(d6, j0 + 6, o6,   o7);
        PUSHB(d7, j0 + 7, o7,   o8);
        offb = o8;

        // Warp-uniform flush trigger; drain is per-lane (R3-style).
        if (__any_sync(0xFFFFFFFFu, offb >= FLUSH_B)) {
            const int cnt = (int)(offb / SLOT_B);
            const unsigned long long* myp = pend + tid;
#pragma unroll 1
            for (int p = 0; p < cnt; ++p) {
                const unsigned long long kk = myp[(size_t)p * TPB];
                unsigned lo_, hi_;
                UNPACK2(lo_, hi_, kk);
                float dc = __uint_as_float(hi_);
                int   ic = (int)lo_;
                if (dc < worst) {          // per-lane divergent guard
#pragma unroll
                    for (int m = 0; m < KP1; ++m) {
                        const bool  sw = dc < bd[m];
                        const float fo = sw ? bd[m] : dc;
                        const int   io = sw ? bi[m] : ic;
                        bd[m] = sw ? dc : bd[m];
                        bi[m] = sw ? ic : bi[m];
                        dc = fo; ic = io;
                    }
                    worst = bd[KP1 - 1];
                }
            }
            offb = 0;
        }
    }

    // Final drain.
    {
        const int cnt = (int)(offb / SLOT_B);
        const unsigned long long* myp = pend + tid;
#pragma unroll 1
        for (int p = 0; p < cnt; ++p) {
            const unsigned long long kk = myp[(size_t)p * TPB];
            unsigned lo_, hi_;
            UNPACK2(lo_, hi_, kk);
            float dc = __uint_as_float(hi_);
            int   ic = (int)lo_;
            if (dc < worst) {
#pragma unroll
                for (int m = 0; m < KP1; ++m) {
                    const bool  sw = dc < bd[m];
                    const float fo = sw ? bd[m] : dc;
                    const int   io = sw ? bi[m] : ic;
                    bd[m] = sw ? dc : bd[m];
                    bi[m] = sw ? ic : bi[m];
                    dc = fo; ic = io;
                }
                worst = bd[KP1 - 1];
            }
        }
    }

    // Emit: drop the single self entry (idx == q, d == +0), keep first K.
    const int    gq = base + q;
    const size_t Nk = (size_t)total_n * K;
    int w = 0;
#pragma unroll
    for (int m = 0; m < KP1; ++m) {
        if (bi[m] != q && w < K) {
            const size_t e = (size_t)gq * K + w;
            out[e]          = (float)(bi[m] + base);
            out[Nk + e]     = (float)gq;
            out[2 * Nk + e] = bd[m];
            ++w;
        }
    }
}

extern "C" void kernel_launch(void* const* d_in, const int* in_sizes, int n_in,
                              void* d_out, int out_size)
{
    const float* pos = (const float*)d_in[0];
    const int total_n = in_sizes[0] / 3;
    const int ngraphs = total_n / NPER;

    const int smem_bytes = 4 * NPER * (int)sizeof(float)
                         + PB * TPB * (int)sizeof(unsigned long long); // 88 KB
    cudaFuncSetAttribute(knn_topk_kernel,
                         cudaFuncAttributeMaxDynamicSharedMemorySize, smem_bytes);

    knn_topk_kernel<<<ngraphs * CPG, TPB, smem_bytes>>>(pos, (float*)d_out, total_n);
}